// round 1
// baseline (speedup 1.0000x reference)
#include <cuda_runtime.h>
#include <math.h>

#define N_NODES 50000
#define DIM 128

// Ping-pong feature buffers (25.6 MB each) — static device globals, no allocation.
__device__ float g_bufA[N_NODES * DIM];
__device__ float g_bufB[N_NODES * DIM];

// ---------------------------------------------------------------------------
// logmap0: h[:,0] = 0 ; h[:,1:] = acosh(max(x0, 1+eps)) * y / max(||y||, 1e-15)
// One warp per node; lane handles one float4 (4 features).
// ---------------------------------------------------------------------------
__global__ void logmap_kernel(const float* __restrict__ x, float* __restrict__ h) {
    int idx  = blockIdx.x * blockDim.x + threadIdx.x;
    int node = idx >> 5;
    int lane = idx & 31;
    if (node >= N_NODES) return;

    float4 a = reinterpret_cast<const float4*>(x + (size_t)node * DIM)[lane];
    float sq = a.x * a.x + a.y * a.y + a.z * a.z + a.w * a.w;
    if (lane == 0) sq -= a.x * a.x;   // exclude time-like coord from ||y||
#pragma unroll
    for (int o = 16; o; o >>= 1) sq += __shfl_xor_sync(0xffffffffu, sq, o);

    float x0    = __shfl_sync(0xffffffffu, a.x, 0);
    float ynorm = fmaxf(sqrtf(sq), 1e-15f);
    float theta = fmaxf(x0, 1.0f + 1e-5f);
    float scale = acoshf(theta) / ynorm;

    float4 o4;
    o4.x = a.x * scale; o4.y = a.y * scale; o4.z = a.z * scale; o4.w = a.w * scale;
    if (lane == 0) o4.x = 0.0f;
    reinterpret_cast<float4*>(h + (size_t)node * DIM)[lane] = o4;
}

// ---------------------------------------------------------------------------
// SpMM (segment_sum): hout[rows[e]] += vals[e] * hin[cols[e]]
// One warp per edge. Lane k handles float4 chunk k of the 128-wide row.
// Gather is 512B fully coalesced; scatter uses vectorized red.global.add.v4.f32
// (4x fewer L2 atomic transactions than scalar atomicAdd).
// ---------------------------------------------------------------------------
__global__ void spmm_kernel(const float* __restrict__ hin, float* __restrict__ hout,
                            const int* __restrict__ rows, const int* __restrict__ cols,
                            const float* __restrict__ vals, int E) {
    int gid  = blockIdx.x * blockDim.x + threadIdx.x;
    int e    = gid >> 5;
    int lane = gid & 31;
    if (e >= E) return;

    int   r = __ldg(rows + e);   // broadcast within warp
    int   c = __ldg(cols + e);
    float v = __ldg(vals + e);

    const float4* src = reinterpret_cast<const float4*>(hin + (size_t)c * DIM);
    float4 a = __ldcg(src + lane);   // .cg: reuse is in L2, skip L1
    a.x *= v; a.y *= v; a.z *= v; a.w *= v;

    float* dst = hout + (size_t)r * DIM + (size_t)lane * 4;
    asm volatile("red.global.add.v4.f32 [%0], {%1, %2, %3, %4};"
                 :: "l"(dst), "f"(a.x), "f"(a.y), "f"(a.z), "f"(a.w)
                 : "memory");
}

// ---------------------------------------------------------------------------
// expmap0 + proj fused:
//   v = h[:,1:]; vn = max(||v||,1e-15)
//   tail = sinh(vn)/vn * v ; first = sqrt(1 + ||tail||^2) = cosh(vn)
// ---------------------------------------------------------------------------
__global__ void expproj_kernel(const float* __restrict__ h, float* __restrict__ out) {
    int idx  = blockIdx.x * blockDim.x + threadIdx.x;
    int node = idx >> 5;
    int lane = idx & 31;
    if (node >= N_NODES) return;

    float4 a = reinterpret_cast<const float4*>(h + (size_t)node * DIM)[lane];
    float sq = a.x * a.x + a.y * a.y + a.z * a.z + a.w * a.w;
    if (lane == 0) sq -= a.x * a.x;   // h[:,0] is exactly 0, but be explicit
#pragma unroll
    for (int o = 16; o; o >>= 1) sq += __shfl_xor_sync(0xffffffffu, sq, o);

    float vn = fmaxf(sqrtf(sq), 1e-15f);
    float sh = sinhf(vn);
    float s  = sh / vn;

    float4 o4;
    o4.x = a.x * s; o4.y = a.y * s; o4.z = a.z * s; o4.w = a.w * s;
    if (lane == 0) o4.x = sqrtf(fmaxf(1.0f + sh * sh, 1e-5f));   // = cosh(vn)
    reinterpret_cast<float4*>(out + (size_t)node * DIM)[lane] = o4;
}

// ---------------------------------------------------------------------------
extern "C" void kernel_launch(void* const* d_in, const int* in_sizes, int n_in,
                              void* d_out, int out_size) {
    const float* x    = (const float*)d_in[0];
    const int*   rows = (const int*)  d_in[1];
    const int*   cols = (const int*)  d_in[2];
    const float* vals = (const float*)d_in[3];
    const int    E    = in_sizes[1];
    float*       out  = (float*)d_out;

    float *bufA, *bufB;
    cudaGetSymbolAddress((void**)&bufA, g_bufA);
    cudaGetSymbolAddress((void**)&bufB, g_bufB);

    const size_t bytes = (size_t)N_NODES * DIM * sizeof(float);

    // node-parallel kernels: 1 warp/node
    int nodeThreads = 256;
    int nodeBlocks  = (N_NODES * 32 + nodeThreads - 1) / nodeThreads;

    // edge-parallel spmm: 1 warp/edge
    long long spThreads = (long long)E * 32;
    int spBlocks = (int)((spThreads + 255) / 256);

    logmap_kernel<<<nodeBlocks, nodeThreads>>>(x, bufA);

    cudaMemsetAsync(bufB, 0, bytes);
    spmm_kernel<<<spBlocks, 256>>>(bufA, bufB, rows, cols, vals, E);

    cudaMemsetAsync(bufA, 0, bytes);
    spmm_kernel<<<spBlocks, 256>>>(bufB, bufA, rows, cols, vals, E);

    cudaMemsetAsync(bufB, 0, bytes);
    spmm_kernel<<<spBlocks, 256>>>(bufA, bufB, rows, cols, vals, E);

    expproj_kernel<<<nodeBlocks, nodeThreads>>>(bufB, out);
}

// round 2
// speedup vs baseline: 2.0383x; 2.0383x over previous
#include <cuda_runtime.h>
#include <math.h>

#define N_NODES 50000
#define DIM     128
#define E_MAX   1600000

// ---- static device scratch (no allocation allowed) ----
__device__ float g_bufA[N_NODES * DIM];          // 25.6 MB
__device__ float g_bufB[N_NODES * DIM];          // 25.6 MB
__device__ int   g_cnt[N_NODES];
__device__ int   g_rowstart[N_NODES + 1];
__device__ int   g_fill[N_NODES];
__device__ int   g_scol[E_MAX];                  // 6.4 MB
__device__ float g_sval[E_MAX];                  // 6.4 MB

// ---------------------------------------------------------------------------
// logmap0: h[:,0]=0 ; h[:,1:] = acosh(max(x0,1+eps)) * y / max(||y||,1e-15)
// One warp per node, lane = one float4 chunk.
// ---------------------------------------------------------------------------
__global__ void logmap_kernel(const float* __restrict__ x, float* __restrict__ h) {
    int idx  = blockIdx.x * blockDim.x + threadIdx.x;
    int node = idx >> 5;
    int lane = idx & 31;
    if (node >= N_NODES) return;

    float4 a = reinterpret_cast<const float4*>(x + (size_t)node * DIM)[lane];
    float sq = a.x * a.x + a.y * a.y + a.z * a.z + a.w * a.w;
    if (lane == 0) sq -= a.x * a.x;
#pragma unroll
    for (int o = 16; o; o >>= 1) sq += __shfl_xor_sync(0xffffffffu, sq, o);

    float x0    = __shfl_sync(0xffffffffu, a.x, 0);
    float ynorm = fmaxf(sqrtf(sq), 1e-15f);
    float theta = fmaxf(x0, 1.0f + 1e-5f);
    float scale = acoshf(theta) / ynorm;

    float4 o4;
    o4.x = a.x * scale; o4.y = a.y * scale; o4.z = a.z * scale; o4.w = a.w * scale;
    if (lane == 0) o4.x = 0.0f;
    reinterpret_cast<float4*>(h + (size_t)node * DIM)[lane] = o4;
}

// ---------------------------------------------------------------------------
// CSR build step 1: histogram of row indices
// ---------------------------------------------------------------------------
__global__ void hist_kernel(const int* __restrict__ rows, int E) {
    int e = blockIdx.x * blockDim.x + threadIdx.x;
    if (e < E) atomicAdd(&g_cnt[rows[e]], 1);
}

// ---------------------------------------------------------------------------
// CSR build step 2: exclusive scan of counts (single block, warp-shuffle scan,
// sequential 1024-wide tiles with carry). 50k elements -> ~49 tiles, few us.
// ---------------------------------------------------------------------------
__global__ void scan_kernel(int n) {
    __shared__ int warpsum[32];
    __shared__ int carry;
    int tid  = threadIdx.x;
    int lane = tid & 31;
    int wid  = tid >> 5;
    if (tid == 0) { carry = 0; g_rowstart[0] = 0; }
    __syncthreads();

    for (int base = 0; base < n; base += 1024) {
        int i = base + tid;
        int v = (i < n) ? g_cnt[i] : 0;
        int s = v;
#pragma unroll
        for (int o = 1; o < 32; o <<= 1) {
            int t = __shfl_up_sync(0xffffffffu, s, o);
            if (lane >= o) s += t;
        }
        if (lane == 31) warpsum[wid] = s;
        __syncthreads();
        if (wid == 0) {
            int w = warpsum[lane];
#pragma unroll
            for (int o = 1; o < 32; o <<= 1) {
                int t = __shfl_up_sync(0xffffffffu, w, o);
                if (lane >= o) w += t;
            }
            warpsum[lane] = w;
        }
        __syncthreads();
        int off  = (wid > 0) ? warpsum[wid - 1] : 0;
        int incl = carry + off + s;
        if (i < n) g_rowstart[i + 1] = incl;
        __syncthreads();
        if (tid == 1023) carry += warpsum[31];
        __syncthreads();
    }
}

// ---------------------------------------------------------------------------
// CSR build step 3: permute (cols, vals) into row-sorted order
// ---------------------------------------------------------------------------
__global__ void scatter_kernel(const int* __restrict__ rows, const int* __restrict__ cols,
                               const float* __restrict__ vals, int E) {
    int e = blockIdx.x * blockDim.x + threadIdx.x;
    if (e >= E) return;
    int pos = atomicAdd(&g_fill[rows[e]], 1);
    g_scol[pos] = cols[e];
    g_sval[pos] = vals[e];
}

// ---------------------------------------------------------------------------
// SpMM, CSR gather form: one warp per output row. Lane k owns float4 chunk k.
// Edge (col,val) pairs loaded cooperatively 32-at-a-time, broadcast via shfl.
// No atomics: each output row written exactly once.
// ---------------------------------------------------------------------------
__global__ void spmm_csr_kernel(const float* __restrict__ hin, float* __restrict__ hout) {
    int gid  = blockIdx.x * blockDim.x + threadIdx.x;
    int row  = gid >> 5;
    int lane = gid & 31;
    if (row >= N_NODES) return;

    int s = g_rowstart[row];
    int e = g_rowstart[row + 1];

    float4 acc = make_float4(0.f, 0.f, 0.f, 0.f);

    for (int base = s; base < e; base += 32) {
        int   j   = base + lane;
        int   c   = (j < e) ? g_scol[j] : 0;
        float v   = (j < e) ? g_sval[j] : 0.0f;
        int   cnt = min(32, e - base);

        if (cnt == 32) {
#pragma unroll
            for (int k = 0; k < 32; k++) {
                int   ck = __shfl_sync(0xffffffffu, c, k);
                float vk = __shfl_sync(0xffffffffu, v, k);
                float4 a = __ldcg(reinterpret_cast<const float4*>(hin + (size_t)ck * DIM) + lane);
                acc.x = fmaf(vk, a.x, acc.x);
                acc.y = fmaf(vk, a.y, acc.y);
                acc.z = fmaf(vk, a.z, acc.z);
                acc.w = fmaf(vk, a.w, acc.w);
            }
        } else {
            for (int k = 0; k < cnt; k++) {
                int   ck = __shfl_sync(0xffffffffu, c, k);
                float vk = __shfl_sync(0xffffffffu, v, k);
                float4 a = __ldcg(reinterpret_cast<const float4*>(hin + (size_t)ck * DIM) + lane);
                acc.x = fmaf(vk, a.x, acc.x);
                acc.y = fmaf(vk, a.y, acc.y);
                acc.z = fmaf(vk, a.z, acc.z);
                acc.w = fmaf(vk, a.w, acc.w);
            }
        }
    }
    reinterpret_cast<float4*>(hout + (size_t)row * DIM)[lane] = acc;
}

// ---------------------------------------------------------------------------
// expmap0 + proj fused
// ---------------------------------------------------------------------------
__global__ void expproj_kernel(const float* __restrict__ h, float* __restrict__ out) {
    int idx  = blockIdx.x * blockDim.x + threadIdx.x;
    int node = idx >> 5;
    int lane = idx & 31;
    if (node >= N_NODES) return;

    float4 a = reinterpret_cast<const float4*>(h + (size_t)node * DIM)[lane];
    float sq = a.x * a.x + a.y * a.y + a.z * a.z + a.w * a.w;
    if (lane == 0) sq -= a.x * a.x;
#pragma unroll
    for (int o = 16; o; o >>= 1) sq += __shfl_xor_sync(0xffffffffu, sq, o);

    float vn = fmaxf(sqrtf(sq), 1e-15f);
    float sh = sinhf(vn);
    float sc = sh / vn;

    float4 o4;
    o4.x = a.x * sc; o4.y = a.y * sc; o4.z = a.z * sc; o4.w = a.w * sc;
    if (lane == 0) o4.x = sqrtf(fmaxf(1.0f + sh * sh, 1e-5f));   // cosh(vn)
    reinterpret_cast<float4*>(out + (size_t)node * DIM)[lane] = o4;
}

// ---------------------------------------------------------------------------
extern "C" void kernel_launch(void* const* d_in, const int* in_sizes, int n_in,
                              void* d_out, int out_size) {
    const float* x    = (const float*)d_in[0];
    const int*   rows = (const int*)  d_in[1];
    const int*   cols = (const int*)  d_in[2];
    const float* vals = (const float*)d_in[3];
    const int    E    = in_sizes[1];
    float*       out  = (float*)d_out;

    float *bufA, *bufB;
    int *cnt, *rowstart, *fill;
    cudaGetSymbolAddress((void**)&bufA, g_bufA);
    cudaGetSymbolAddress((void**)&bufB, g_bufB);
    cudaGetSymbolAddress((void**)&cnt,  g_cnt);
    cudaGetSymbolAddress((void**)&rowstart, g_rowstart);
    cudaGetSymbolAddress((void**)&fill, g_fill);

    int nodeThreads = 256;
    int nodeBlocks  = (N_NODES * 32 + nodeThreads - 1) / nodeThreads;
    int edgeBlocks  = (E + 255) / 256;

    // ---- CSR build (edge list identical for all layers; rebuilt each call) ----
    cudaMemsetAsync(cnt, 0, N_NODES * sizeof(int));
    hist_kernel<<<edgeBlocks, 256>>>(rows, E);
    scan_kernel<<<1, 1024>>>(N_NODES);
    cudaMemcpyAsync(fill, rowstart, N_NODES * sizeof(int), cudaMemcpyDeviceToDevice);
    scatter_kernel<<<edgeBlocks, 256>>>(rows, cols, vals, E);

    // ---- pipeline ----
    logmap_kernel<<<nodeBlocks, nodeThreads>>>(x, bufA);
    spmm_csr_kernel<<<nodeBlocks, nodeThreads>>>(bufA, bufB);
    spmm_csr_kernel<<<nodeBlocks, nodeThreads>>>(bufB, bufA);
    spmm_csr_kernel<<<nodeBlocks, nodeThreads>>>(bufA, bufB);
    expproj_kernel<<<nodeBlocks, nodeThreads>>>(bufB, out);
}